// round 7
// baseline (speedup 1.0000x reference)
#include <cuda_runtime.h>

#define BB 512
#define TT 256

typedef unsigned long long u64;

// Inter-layer hidden sequences, batch-major [B, T, H]. Max H=256 -> 128 MB each.
__device__ float g_bufA[BB * TT * 256];
__device__ float g_bufB[BB * TT * 256];

__device__ __forceinline__ void ffma2(u64& d, u64 a, u64 b) {
    // packed fp32x2 fma: d.lo += a.lo*b.lo ; d.hi += a.hi*b.hi (IEEE per lane)
    asm("fma.rn.f32x2 %0, %1, %2, %0;" : "+l"(d) : "l"(a), "l"(b));
}

// One kernel per layer. grid = 128 CTAs (BT=4 batch rows), block = THREADS.
// Thread (jp = tid % NPAIR, p = tid / NPAIR) owns the adjacent output-column
// PAIR (2jp, 2jp+1) and the p-th slice of the virtual weight rows [Wx; Wh].
// Weight pairs (w_2jp, w_2jp+1) are adjacent in memory -> loaded ONCE as 8B
// pairs into registers (KREG) or smem (KSM rows), no packing movs ever.
// Activations live in smem DUPLICATED: abuf[buf][k][r] = (v,v), written once
// per element per step. Inner loop per k: 2 uniform LDS.128 + 4 FFMA2 -> 8
// outputs. Partials combined P-way through smem (2 barriers/step); the
// combine loops CNT times so BT*NPAIR elements are covered even when
// BT*NPAIR > THREADS (layer 2!).
template<int FIN, int H, int P, int KREG, int THREADS, bool FUSE_DENSE>
__global__ void __launch_bounds__(THREADS, 1)
rnn_layer(const float* __restrict__ x,     // [B, T, FIN]
          const float* __restrict__ Wx,    // [FIN, H]
          const float* __restrict__ Wh,    // [H, H]
          const float* __restrict__ bias,  // [H]
          float* __restrict__ hout,        // [B, T, H]
          const float* __restrict__ Wd,    // [T*H, 1] (FUSE_DENSE)
          const float* __restrict__ bd,    // [1]
          float* __restrict__ out)         // [B]     (FUSE_DENSE)
{
    constexpr int BT    = 4;
    constexpr int NPAIR = H / 2;
    constexpr int KV    = FIN + H;
    constexpr int KS    = KV / P;
    constexpr int KSM   = KS - KREG;
    constexpr int CNTX  = (BT * FIN + THREADS - 1) / THREADS;
    constexpr int CNT   = (BT * NPAIR + THREADS - 1) / THREADS;  // combine elems/thread
    constexpr int REDN  = FUSE_DENSE ? THREADS : 1;
    static_assert(NPAIR * P == THREADS, "thread count");
    static_assert(KV % P == 0 && KSM >= 0, "k partition");
    static_assert(NPAIR % 32 == 0, "warp-uniform k per warp");
    static_assert(!FUSE_DENSE || CNT == 1, "dense fusion assumes CNT==1");

    extern __shared__ float2 wsm[];                       // [P][KSM][NPAIR]
    __shared__ __align__(16) float2 abuf[2][KV][BT];      // duplicated acts (v,v)
    __shared__ __align__(16) float2 part[P][BT][NPAIR];
    __shared__ float red[REDN];

    const int tid = threadIdx.x;
    const int jp  = tid % NPAIR;
    const int p   = tid / NPAIR;
    const int b0  = blockIdx.x * BT;
    const int k0  = p * KS;

    // ---- one-time: register-resident weight pairs ----
    u64 w[KREG > 0 ? KREG : 1];
    #pragma unroll
    for (int q = 0; q < KREG; ++q) {
        int v = k0 + q;
        const float* src = (v < FIN) ? &Wx[v * H + 2 * jp]
                                     : &Wh[(v - FIN) * H + 2 * jp];
        w[q] = *(const u64*)src;
    }
    // ---- one-time: smem-resident weight pairs ----
    if (KSM > 0) {
        for (int idx = tid; idx < P * KSM * NPAIR; idx += THREADS) {
            int pp = idx / (KSM * NPAIR);
            int s  = (idx / NPAIR) % KSM;
            int jj = idx % NPAIR;
            int v  = pp * KS + KREG + s;
            const float* src = (v < FIN) ? &Wx[v * H + 2 * jj]
                                         : &Wh[(v - FIN) * H + 2 * jj];
            wsm[idx] = *(const float2*)src;
        }
    }
    // h_0 = 0 (duplicated layout)
    for (int i = tid; i < H * BT; i += THREADS)
        abuf[0][FIN + i / BT][i % BT] = make_float2(0.f, 0.f);
    // prime x(t=0)
    #pragma unroll
    for (int q = 0; q < CNTX; ++q) {
        int i = tid + q * THREADS;
        if (i < BT * FIN) {
            int r = i / FIN, k = i % FIN;
            float v = __ldcg(&x[((b0 + r) * TT + 0) * FIN + k]);
            abuf[0][k][r] = make_float2(v, v);
        }
    }
    // combine-role constants: element e = tid + q*THREADS -> (row er, pair ej)
    float2 b2[CNT];
    #pragma unroll
    for (int q = 0; q < CNT; ++q) {
        int e = tid + q * THREADS;
        b2[q] = (e < BT * NPAIR) ? *(const float2*)&bias[2 * (e % NPAIR)]
                                 : make_float2(0.f, 0.f);
    }

    __syncthreads();

    float dacc = 0.f;
    int cb = 0;

    for (int t = 0; t < TT; ++t) {
        const int nb = cb ^ 1;

        // prefetch x(t+1) into regs (hidden behind FFMA phase)
        float xst[CNTX];
        if (t + 1 < TT) {
            #pragma unroll
            for (int q = 0; q < CNTX; ++q) {
                int i = tid + q * THREADS;
                if (i < BT * FIN)
                    xst[q] = __ldcg(&x[((b0 + i / FIN) * TT + (t + 1)) * FIN + (i % FIN)]);
            }
        }

        u64 a0 = 0, a1 = 0, a2 = 0, a3 = 0;

        #pragma unroll
        for (int q = 0; q < KREG; ++q) {          // register weight pairs
            const int k = k0 + q;
            ulonglong2 lo = *(const ulonglong2*)&abuf[cb][k][0];  // (r0,r0|r1,r1)
            ulonglong2 hi = *(const ulonglong2*)&abuf[cb][k][2];  // (r2,r2|r3,r3)
            ffma2(a0, lo.x, w[q]);
            ffma2(a1, lo.y, w[q]);
            ffma2(a2, hi.x, w[q]);
            ffma2(a3, hi.y, w[q]);
        }
        if (KSM > 0) {                             // smem weight pairs (LDS.64)
            const float2* wp = wsm + (p * KSM) * NPAIR + jp;
            #pragma unroll 4
            for (int s = 0; s < KSM; ++s) {
                const int k = k0 + KREG + s;
                ulonglong2 lo = *(const ulonglong2*)&abuf[cb][k][0];
                ulonglong2 hi = *(const ulonglong2*)&abuf[cb][k][2];
                u64 wv = *(const u64*)&wp[s * NPAIR];
                ffma2(a0, lo.x, wv);
                ffma2(a1, lo.y, wv);
                ffma2(a2, hi.x, wv);
                ffma2(a3, hi.y, wv);
            }
        }

        // park partials (pairs, conflict-free STS.64)
        part[p][0][jp] = *(float2*)&a0;
        part[p][1][jp] = *(float2*)&a1;
        part[p][2][jp] = *(float2*)&a2;
        part[p][3][jp] = *(float2*)&a3;
        // commit staged x into the next buffer
        if (t + 1 < TT) {
            #pragma unroll
            for (int q = 0; q < CNTX; ++q) {
                int i = tid + q * THREADS;
                if (i < BT * FIN)
                    abuf[nb][i % FIN][i / FIN] = make_float2(xst[q], xst[q]);
            }
        }
        __syncthreads();

        // combine: P-way sum, bias, relu, state update (+dense / hout)
        #pragma unroll
        for (int q = 0; q < CNT; ++q) {
            int e = tid + q * THREADS;
            if (e < BT * NPAIR) {
                int er = e / NPAIR, ej = e % NPAIR;
                float2 s = b2[q];
                #pragma unroll
                for (int pp = 0; pp < P; ++pp) {
                    float2 pv = part[pp][er][ej];
                    s.x += pv.x; s.y += pv.y;
                }
                s.x = fmaxf(s.x, 0.f);
                s.y = fmaxf(s.y, 0.f);
                abuf[nb][FIN + 2 * ej][er]     = make_float2(s.x, s.x);
                abuf[nb][FIN + 2 * ej + 1][er] = make_float2(s.y, s.y);
                if (FUSE_DENSE) {
                    float2 wd = *(const float2*)&Wd[t * H + 2 * ej];
                    dacc = fmaf(s.x, wd.x, fmaf(s.y, wd.y, dacc));
                } else {
                    __stcg((float2*)&hout[((b0 + er) * TT + t) * H + 2 * ej], s);
                }
            }
        }
        __syncthreads();
        cb = nb;
    }

    if (FUSE_DENSE) {
        red[tid] = dacc;           // e = er*NPAIR + ej; inactive threads wrote 0
        __syncthreads();
        if (tid < BT) {
            float s = bd[0];
            #pragma unroll 8
            for (int i = 0; i < NPAIR; ++i) s += red[tid * NPAIR + i];
            out[b0 + tid] = s;
        }
    }
}

extern "C" void kernel_launch(void* const* d_in, const int* in_sizes, int n_in,
                              void* d_out, int out_size)
{
    (void)in_sizes; (void)n_in; (void)out_size;

    const float* x   = (const float*)d_in[0];
    const float* Wx1 = (const float*)d_in[1];
    const float* Wh1 = (const float*)d_in[2];
    const float* b1  = (const float*)d_in[3];
    const float* Wx2 = (const float*)d_in[4];
    const float* Wh2 = (const float*)d_in[5];
    const float* b2  = (const float*)d_in[6];
    const float* Wx3 = (const float*)d_in[7];
    const float* Wh3 = (const float*)d_in[8];
    const float* b3  = (const float*)d_in[9];
    const float* Wx4 = (const float*)d_in[10];
    const float* Wh4 = (const float*)d_in[11];
    const float* b4  = (const float*)d_in[12];
    const float* Wd  = (const float*)d_in[13];
    const float* bd  = (const float*)d_in[14];
    float* out = (float*)d_out;

    float *bufA = nullptr, *bufB = nullptr;
    cudaGetSymbolAddress((void**)&bufA, g_bufA);
    cudaGetSymbolAddress((void**)&bufB, g_bufB);

    const dim3 grid(BB / 4);   // 128 CTAs

    // Dynamic smem (weight-pair overflow):
    //   L2: P=2, KSM=92,  NPAIR=128 -> 2*92*128*8  = 188416 B
    //   L3: P=8, KSM=16,  NPAIR=64  -> 8*16*64*8   = 65536 B
    constexpr int DynL2 = 2 * 92 * 128 * 8;
    constexpr int DynL3 = 8 * 16 * 64 * 8;
    cudaFuncSetAttribute(rnn_layer<128, 256, 2, 100, 256, false>,
                         cudaFuncAttributeMaxDynamicSharedMemorySize, DynL2);
    cudaFuncSetAttribute(rnn_layer<256, 128, 8, 32, 512, false>,
                         cudaFuncAttributeMaxDynamicSharedMemorySize, DynL3);

    // L1: FIN=64,  H=128: 512 thr, P=8,  KS=24,  all weights in regs (48)
    rnn_layer<64, 128, 8, 24, 512, false><<<grid, 512, 0>>>(
        x, Wx1, Wh1, b1, bufA, nullptr, nullptr, nullptr);
    // L2: FIN=128, H=256: 256 thr, P=2,  KS=192, 100 reg-pairs + 92 smem rows
    rnn_layer<128, 256, 2, 100, 256, false><<<grid, 256, DynL2>>>(
        bufA, Wx2, Wh2, b2, bufB, nullptr, nullptr, nullptr);
    // L3: FIN=256, H=128: 512 thr, P=8,  KS=48,  32 reg-pairs + 16 smem rows
    rnn_layer<256, 128, 8, 32, 512, false><<<grid, 512, DynL3>>>(
        bufB, Wx3, Wh3, b3, bufA, nullptr, nullptr, nullptr);
    // L4: FIN=128, H=64:  512 thr, P=16, KS=12,  all regs, fused final dense
    rnn_layer<128, 64, 16, 12, 512, true><<<grid, 512, 0>>>(
        bufA, Wx4, Wh4, b4, nullptr, Wd, bd, out);
}

// round 8
// speedup vs baseline: 1.0404x; 1.0404x over previous
#include <cuda_runtime.h>

#define BB 512
#define TT 256

typedef unsigned long long u64;

// Inter-layer hidden sequences, batch-major [B, T, H]. Max H=256 -> 128 MB each.
__device__ float g_bufA[BB * TT * 256];
__device__ float g_bufB[BB * TT * 256];

__device__ __forceinline__ void ffma2(u64& d, u64 a, u64 b) {
    // packed fp32x2 fma: d.lo += a.lo*b.lo ; d.hi += a.hi*b.hi (IEEE per lane)
    asm("fma.rn.f32x2 %0, %1, %2, %0;" : "+l"(d) : "l"(a), "l"(b));
}

// One kernel per layer. grid = 128 CTAs (BT=4 batch rows), block = THREADS.
// Thread (jp = tid % NPAIR, p = tid / NPAIR) owns the adjacent output-column
// PAIR (2jp, 2jp+1) and the p-th slice of the virtual weight rows [Wx; Wh].
// Weight pairs (w_2jp, w_2jp+1) are adjacent in memory -> loaded ONCE as 8B
// pairs into registers (KREG) or smem (KSM rows), no packing movs ever.
// Activations live in smem DUPLICATED: abuf[buf][k][r] = (v,v), written once
// per element per step. Inner loop per k: 2 uniform LDS.128 + 4 FFMA2 -> 8
// outputs. Partials combined P-way through smem (2 barriers/step); the
// combine loops CNT times so BT*NPAIR elements are covered even when
// BT*NPAIR > THREADS (layer 2).
// Geometry rule (R6 lesson): keep KS >= ~24 and P <= 8 so per-step fixed
// overheads (barriers, combine, prefetch) stay amortized.
template<int FIN, int H, int P, int KREG, int THREADS, bool FUSE_DENSE>
__global__ void __launch_bounds__(THREADS, 1)
rnn_layer(const float* __restrict__ x,     // [B, T, FIN]
          const float* __restrict__ Wx,    // [FIN, H]
          const float* __restrict__ Wh,    // [H, H]
          const float* __restrict__ bias,  // [H]
          float* __restrict__ hout,        // [B, T, H]
          const float* __restrict__ Wd,    // [T*H, 1] (FUSE_DENSE)
          const float* __restrict__ bd,    // [1]
          float* __restrict__ out)         // [B]     (FUSE_DENSE)
{
    constexpr int BT    = 4;
    constexpr int NPAIR = H / 2;
    constexpr int KV    = FIN + H;
    constexpr int KS    = KV / P;
    constexpr int KSM   = KS - KREG;
    constexpr int CNTX  = (BT * FIN + THREADS - 1) / THREADS;
    constexpr int CNT   = (BT * NPAIR + THREADS - 1) / THREADS;  // combine elems/thread
    constexpr int REDN  = FUSE_DENSE ? THREADS : 1;
    static_assert(NPAIR * P == THREADS, "thread count");
    static_assert(KV % P == 0 && KSM >= 0, "k partition");
    static_assert(NPAIR % 32 == 0, "warp-uniform k per warp");
    static_assert(!FUSE_DENSE || CNT == 1, "dense fusion assumes CNT==1");

    extern __shared__ float2 wsm[];                       // [P][KSM][NPAIR]
    __shared__ __align__(16) float2 abuf[2][KV][BT];      // duplicated acts (v,v)
    __shared__ __align__(16) float2 part[P][BT][NPAIR];
    __shared__ float red[REDN];

    const int tid = threadIdx.x;
    const int jp  = tid % NPAIR;
    const int p   = tid / NPAIR;
    const int b0  = blockIdx.x * BT;
    const int k0  = p * KS;

    // ---- one-time: register-resident weight pairs ----
    u64 w[KREG > 0 ? KREG : 1];
    #pragma unroll
    for (int q = 0; q < KREG; ++q) {
        int v = k0 + q;
        const float* src = (v < FIN) ? &Wx[v * H + 2 * jp]
                                     : &Wh[(v - FIN) * H + 2 * jp];
        w[q] = *(const u64*)src;
    }
    // ---- one-time: smem-resident weight pairs ----
    if (KSM > 0) {
        for (int idx = tid; idx < P * KSM * NPAIR; idx += THREADS) {
            int pp = idx / (KSM * NPAIR);
            int s  = (idx / NPAIR) % KSM;
            int jj = idx % NPAIR;
            int v  = pp * KS + KREG + s;
            const float* src = (v < FIN) ? &Wx[v * H + 2 * jj]
                                         : &Wh[(v - FIN) * H + 2 * jj];
            wsm[idx] = *(const float2*)src;
        }
    }
    // h_0 = 0 (duplicated layout)
    for (int i = tid; i < H * BT; i += THREADS)
        abuf[0][FIN + i / BT][i % BT] = make_float2(0.f, 0.f);
    // prime x(t=0)
    #pragma unroll
    for (int q = 0; q < CNTX; ++q) {
        int i = tid + q * THREADS;
        if (i < BT * FIN) {
            int r = i / FIN, k = i % FIN;
            float v = __ldcg(&x[((b0 + r) * TT + 0) * FIN + k]);
            abuf[0][k][r] = make_float2(v, v);
        }
    }
    // combine-role constants: element e = tid + q*THREADS -> (row er, pair ej)
    float2 b2[CNT];
    #pragma unroll
    for (int q = 0; q < CNT; ++q) {
        int e = tid + q * THREADS;
        b2[q] = (e < BT * NPAIR) ? *(const float2*)&bias[2 * (e % NPAIR)]
                                 : make_float2(0.f, 0.f);
    }

    __syncthreads();

    float dacc = 0.f;
    int cb = 0;

    for (int t = 0; t < TT; ++t) {
        const int nb = cb ^ 1;

        // prefetch x(t+1) into regs (hidden behind FFMA phase)
        float xst[CNTX];
        if (t + 1 < TT) {
            #pragma unroll
            for (int q = 0; q < CNTX; ++q) {
                int i = tid + q * THREADS;
                if (i < BT * FIN)
                    xst[q] = __ldcg(&x[((b0 + i / FIN) * TT + (t + 1)) * FIN + (i % FIN)]);
            }
        }

        u64 a0 = 0, a1 = 0, a2 = 0, a3 = 0;

        #pragma unroll
        for (int q = 0; q < KREG; ++q) {          // register weight pairs
            const int k = k0 + q;
            ulonglong2 lo = *(const ulonglong2*)&abuf[cb][k][0];  // (r0,r0|r1,r1)
            ulonglong2 hi = *(const ulonglong2*)&abuf[cb][k][2];  // (r2,r2|r3,r3)
            ffma2(a0, lo.x, w[q]);
            ffma2(a1, lo.y, w[q]);
            ffma2(a2, hi.x, w[q]);
            ffma2(a3, hi.y, w[q]);
        }
        if (KSM > 0) {                             // smem weight pairs (LDS.64)
            const float2* wp = wsm + (p * KSM) * NPAIR + jp;
            #pragma unroll 4
            for (int s = 0; s < KSM; ++s) {
                const int k = k0 + KREG + s;
                ulonglong2 lo = *(const ulonglong2*)&abuf[cb][k][0];
                ulonglong2 hi = *(const ulonglong2*)&abuf[cb][k][2];
                u64 wv = *(const u64*)&wp[s * NPAIR];
                ffma2(a0, lo.x, wv);
                ffma2(a1, lo.y, wv);
                ffma2(a2, hi.x, wv);
                ffma2(a3, hi.y, wv);
            }
        }

        // park partials (pairs, conflict-free STS.64)
        part[p][0][jp] = *(float2*)&a0;
        part[p][1][jp] = *(float2*)&a1;
        part[p][2][jp] = *(float2*)&a2;
        part[p][3][jp] = *(float2*)&a3;
        // commit staged x into the next buffer
        if (t + 1 < TT) {
            #pragma unroll
            for (int q = 0; q < CNTX; ++q) {
                int i = tid + q * THREADS;
                if (i < BT * FIN)
                    abuf[nb][i % FIN][i / FIN] = make_float2(xst[q], xst[q]);
            }
        }
        __syncthreads();

        // combine: P-way sum, bias, relu, state update (+dense / hout)
        #pragma unroll
        for (int q = 0; q < CNT; ++q) {
            int e = tid + q * THREADS;
            if (e < BT * NPAIR) {
                int er = e / NPAIR, ej = e % NPAIR;
                float2 s = b2[q];
                #pragma unroll
                for (int pp = 0; pp < P; ++pp) {
                    float2 pv = part[pp][er][ej];
                    s.x += pv.x; s.y += pv.y;
                }
                s.x = fmaxf(s.x, 0.f);
                s.y = fmaxf(s.y, 0.f);
                abuf[nb][FIN + 2 * ej][er]     = make_float2(s.x, s.x);
                abuf[nb][FIN + 2 * ej + 1][er] = make_float2(s.y, s.y);
                if (FUSE_DENSE) {
                    float2 wd = *(const float2*)&Wd[t * H + 2 * ej];
                    dacc = fmaf(s.x, wd.x, fmaf(s.y, wd.y, dacc));
                } else {
                    __stcg((float2*)&hout[((b0 + er) * TT + t) * H + 2 * ej], s);
                }
            }
        }
        __syncthreads();
        cb = nb;
    }

    if (FUSE_DENSE) {
        red[tid] = dacc;           // e = er*NPAIR + ej; inactive threads wrote 0
        __syncthreads();
        if (tid < BT) {
            float s = bd[0];
            #pragma unroll 8
            for (int i = 0; i < NPAIR; ++i) s += red[tid * NPAIR + i];
            out[b0 + tid] = s;
        }
    }
}

extern "C" void kernel_launch(void* const* d_in, const int* in_sizes, int n_in,
                              void* d_out, int out_size)
{
    (void)in_sizes; (void)n_in; (void)out_size;

    const float* x   = (const float*)d_in[0];
    const float* Wx1 = (const float*)d_in[1];
    const float* Wh1 = (const float*)d_in[2];
    const float* b1  = (const float*)d_in[3];
    const float* Wx2 = (const float*)d_in[4];
    const float* Wh2 = (const float*)d_in[5];
    const float* b2  = (const float*)d_in[6];
    const float* Wx3 = (const float*)d_in[7];
    const float* Wh3 = (const float*)d_in[8];
    const float* b3  = (const float*)d_in[9];
    const float* Wx4 = (const float*)d_in[10];
    const float* Wh4 = (const float*)d_in[11];
    const float* b4  = (const float*)d_in[12];
    const float* Wd  = (const float*)d_in[13];
    const float* bd  = (const float*)d_in[14];
    float* out = (float*)d_out;

    float *bufA = nullptr, *bufB = nullptr;
    cudaGetSymbolAddress((void**)&bufA, g_bufA);
    cudaGetSymbolAddress((void**)&bufB, g_bufB);

    const dim3 grid(BB / 4);   // 128 CTAs

    // Dynamic smem (weight-pair overflow):
    //   L2: P=2, KSM=92, NPAIR=128 -> 2*92*128*8 = 188416 B
    //   L3: P=4, KSM=32, NPAIR=64  -> 4*32*64*8  = 65536 B
    constexpr int DynL2 = 2 * 92 * 128 * 8;
    constexpr int DynL3 = 4 * 32 * 64 * 8;
    cudaFuncSetAttribute(rnn_layer<128, 256, 2, 100, 256, false>,
                         cudaFuncAttributeMaxDynamicSharedMemorySize, DynL2);
    cudaFuncSetAttribute(rnn_layer<256, 128, 4, 64, 256, false>,
                         cudaFuncAttributeMaxDynamicSharedMemorySize, DynL3);

    // L1: FIN=64,  H=128: 256 thr, P=4, KS=48,  all 48 weight-pairs in regs
    rnn_layer<64, 128, 4, 48, 256, false><<<grid, 256, 0>>>(
        x, Wx1, Wh1, b1, bufA, nullptr, nullptr, nullptr);
    // L2: FIN=128, H=256: 256 thr, P=2, KS=192, 100 reg-pairs + 92 smem rows
    rnn_layer<128, 256, 2, 100, 256, false><<<grid, 256, DynL2>>>(
        bufA, Wx2, Wh2, b2, bufB, nullptr, nullptr, nullptr);
    // L3: FIN=256, H=128: 256 thr, P=4, KS=96,  64 reg-pairs + 32 smem rows
    rnn_layer<256, 128, 4, 64, 256, false><<<grid, 256, DynL3>>>(
        bufB, Wx3, Wh3, b3, bufA, nullptr, nullptr, nullptr);
    // L4: FIN=128, H=64:  256 thr, P=8, KS=24,  all in regs, fused final dense
    rnn_layer<128, 64, 8, 24, 256, true><<<grid, 256, 0>>>(
        bufA, Wx4, Wh4, b4, nullptr, Wd, bd, out);
}

// round 9
// speedup vs baseline: 1.1395x; 1.0952x over previous
#include <cuda_runtime.h>

#define BB 512
#define TT 256

// Inter-layer hidden sequences, batch-major [B, T, H]. Max H=256 -> 128 MB each.
__device__ float g_bufA[BB * TT * 256];
__device__ float g_bufB[BB * TT * 256];

// One kernel per layer. grid = 128 CTAs (BT=4 batch rows each), block = THREADS.
// Thread (j = tid % H, p = tid / H) owns output column j and the p-th slice of
// the virtual weight rows [Wx; Wh] (FIN+H rows). Its KS = (FIN+H)/P weight
// values are loop-invariant: the first KREG live in REGISTERS (loaded once),
// the remaining KSM rows live in (dynamic) shared memory. Activations are
// k-major: buf[2][FIN+H] of float4 = (r0,r1,r2,r3) at virtual row k, so the
// inner loop is: 1 uniform LDS.128 + 4 FFMA per k, zero global traffic.
// P==1 (layer 2): thread owns the full column -> no partial combine, ONE
// barrier per step. P>1: partials through smem, two barriers per step.
// R8: THREADS is a template param; small-smem layers run 512 threads
// (4 warps/SMSP) purely for latency hiding -- per-SM work is conserved.
template<int FIN, int H, int P, int KREG, int THREADS, bool FUSE_DENSE>
__global__ void __launch_bounds__(THREADS, 1)
rnn_layer(const float* __restrict__ x,     // [B, T, FIN]
          const float* __restrict__ Wx,    // [FIN, H]
          const float* __restrict__ Wh,    // [H, H]
          const float* __restrict__ bias,  // [H]
          float* __restrict__ hout,        // [B, T, H]
          const float* __restrict__ Wd,    // [T*H, 1] (FUSE_DENSE)
          const float* __restrict__ bd,    // [1]
          float* __restrict__ out)         // [B]     (FUSE_DENSE)
{
    constexpr int BT  = 4;
    constexpr int KV  = FIN + H;          // virtual k rows
    constexpr int KS  = KV / P;           // rows per partition
    constexpr int KSM = KS - KREG;        // smem-resident rows per partition
    constexpr int CNT  = (BT * H + THREADS - 1) / THREADS;   // combine elems/thread
    constexpr int CNTX = (BT * FIN + THREADS - 1) / THREADS; // x-stage elems/thread
    constexpr int REDN = FUSE_DENSE ? THREADS : 1;
    static_assert(H * P == THREADS, "thread count");
    static_assert(KV % P == 0 && KSM >= 0, "k partition");
    static_assert(!FUSE_DENSE || CNT == 1, "dense fusion assumes CNT==1");

    extern __shared__ float ws[];                       // [P][KSM][H]
    __shared__ __align__(16) float4 buf[2][KV];         // x rows then h rows
    __shared__ float part[(P > 1 ? P : 1)][BT][(P > 1 ? H : 1)];
    __shared__ float red[REDN];

    const int tid = threadIdx.x;
    const int j   = tid % H;
    const int p   = tid / H;
    const int b0  = blockIdx.x * BT;
    const int k0  = p * KS;

    // ---- one-time: register-resident weights (column j, rows k0..k0+KREG) ----
    float w[KREG > 0 ? KREG : 1];
    #pragma unroll
    for (int q = 0; q < KREG; ++q) {
        int v = k0 + q;
        w[q] = (v < FIN) ? __ldg(&Wx[v * H + j]) : __ldg(&Wh[(v - FIN) * H + j]);
    }
    // ---- one-time: smem-resident weight overflow ----
    if (KSM > 0) {
        for (int idx = tid; idx < P * KSM * H; idx += THREADS) {
            int pp = idx / (KSM * H);
            int rem = idx % (KSM * H);
            int s = rem / H, jj = rem % H;
            int v = pp * KS + KREG + s;
            ws[idx] = (v < FIN) ? Wx[v * H + jj] : Wh[(v - FIN) * H + jj];
        }
    }
    // h_0 = 0
    for (int i = tid; i < H; i += THREADS) buf[0][FIN + i] = make_float4(0.f, 0.f, 0.f, 0.f);
    // prime x(t=0)
    #pragma unroll
    for (int q = 0; q < CNTX; ++q) {
        int i = tid + q * THREADS;
        if (i < BT * FIN) {
            int r = i / FIN, k = i % FIN;
            ((float*)buf[0])[k * 4 + r] = __ldcg(&x[((b0 + r) * TT + 0) * FIN + k]);
        }
    }

    const float bjj = bias[j];     // P==1 path
    float bj[CNT];                 // P>1 combine path
    #pragma unroll
    for (int q = 0; q < CNT; ++q) {
        int e = tid + q * THREADS;
        bj[q] = (e < BT * H) ? bias[e % H] : 0.f;
    }

    __syncthreads();

    float dacc = 0.f;
    int cb = 0;

    for (int t = 0; t < TT; ++t) {
        const int nb = cb ^ 1;

        // prefetch x(t+1) into regs (latency hidden behind FFMA phase)
        float xst[CNTX];
        if (t + 1 < TT) {
            #pragma unroll
            for (int q = 0; q < CNTX; ++q) {
                int i = tid + q * THREADS;
                if (i < BT * FIN)
                    xst[q] = __ldcg(&x[((b0 + i / FIN) * TT + (t + 1)) * FIN + (i % FIN)]);
            }
        }

        float a0 = 0.f, a1 = 0.f, a2 = 0.f, a3 = 0.f;
        const float4* ub = buf[cb] + k0;

        #pragma unroll
        for (int q = 0; q < KREG; ++q) {        // register weights
            float4 v = ub[q];
            a0 = fmaf(v.x, w[q], a0);
            a1 = fmaf(v.y, w[q], a1);
            a2 = fmaf(v.z, w[q], a2);
            a3 = fmaf(v.w, w[q], a3);
        }
        if (KSM > 0) {                           // smem weights (coalesced LDS)
            const float* wsp = ws + (p * KSM) * H + j;
            #pragma unroll 8
            for (int s = 0; s < KSM; ++s) {
                float4 v = ub[KREG + s];
                float wv = wsp[s * H];
                a0 = fmaf(v.x, wv, a0);
                a1 = fmaf(v.y, wv, a1);
                a2 = fmaf(v.z, wv, a2);
                a3 = fmaf(v.w, wv, a3);
            }
        }

        if (P == 1) {
            // full column owned by this thread: relu + direct state update
            float4 hv;
            hv.x = fmaxf(a0 + bjj, 0.f);
            hv.y = fmaxf(a1 + bjj, 0.f);
            hv.z = fmaxf(a2 + bjj, 0.f);
            hv.w = fmaxf(a3 + bjj, 0.f);
            buf[nb][FIN + j] = hv;               // STS.128
            if (t + 1 < TT) {
                #pragma unroll
                for (int q = 0; q < CNTX; ++q) {
                    int i = tid + q * THREADS;
                    if (i < BT * FIN)
                        ((float*)buf[nb])[(i % FIN) * 4 + (i / FIN)] = xst[q];
                }
            }
            __stcg(&hout[((b0 + 0) * TT + t) * H + j], hv.x);
            __stcg(&hout[((b0 + 1) * TT + t) * H + j], hv.y);
            __stcg(&hout[((b0 + 2) * TT + t) * H + j], hv.z);
            __stcg(&hout[((b0 + 3) * TT + t) * H + j], hv.w);
            __syncthreads();                     // ONE barrier per step
        } else {
            part[p][0][j] = a0;
            part[p][1][j] = a1;
            part[p][2][j] = a2;
            part[p][3][j] = a3;
            if (t + 1 < TT) {
                #pragma unroll
                for (int q = 0; q < CNTX; ++q) {
                    int i = tid + q * THREADS;
                    if (i < BT * FIN)
                        ((float*)buf[nb])[(i % FIN) * 4 + (i / FIN)] = xst[q];
                }
            }
            __syncthreads();
            #pragma unroll
            for (int q = 0; q < CNT; ++q) {
                int e = tid + q * THREADS;
                if (e < BT * H) {
                    int r = e / H, jj = e % H;
                    float s = bj[q];
                    #pragma unroll
                    for (int pp = 0; pp < P; ++pp) s += part[pp][r][jj];
                    s = fmaxf(s, 0.f);
                    ((float*)buf[nb])[(FIN + jj) * 4 + r] = s;
                    if (FUSE_DENSE) {
                        dacc = fmaf(s, __ldg(&Wd[t * H + jj]), dacc);
                    } else {
                        __stcg(&hout[((b0 + r) * TT + t) * H + jj], s);
                    }
                }
            }
            __syncthreads();
        }
        cb = nb;
    }

    if (FUSE_DENSE) {
        red[tid] = dacc;                  // e = r*H + jj (CNT==1); extras wrote 0
        __syncthreads();
        if (tid < BT) {
            float s = bd[0];
            #pragma unroll 8
            for (int q = 0; q < H; ++q) s += red[tid * H + q];
            out[b0 + tid] = s;
        }
    }
}

extern "C" void kernel_launch(void* const* d_in, const int* in_sizes, int n_in,
                              void* d_out, int out_size)
{
    (void)in_sizes; (void)n_in; (void)out_size;

    const float* x   = (const float*)d_in[0];
    const float* Wx1 = (const float*)d_in[1];
    const float* Wh1 = (const float*)d_in[2];
    const float* b1  = (const float*)d_in[3];
    const float* Wx2 = (const float*)d_in[4];
    const float* Wh2 = (const float*)d_in[5];
    const float* b2  = (const float*)d_in[6];
    const float* Wx3 = (const float*)d_in[7];
    const float* Wh3 = (const float*)d_in[8];
    const float* b3  = (const float*)d_in[9];
    const float* Wx4 = (const float*)d_in[10];
    const float* Wh4 = (const float*)d_in[11];
    const float* b4  = (const float*)d_in[12];
    const float* Wd  = (const float*)d_in[13];
    const float* bd  = (const float*)d_in[14];
    float* out = (float*)d_out;

    float *bufA = nullptr, *bufB = nullptr;
    cudaGetSymbolAddress((void**)&bufA, g_bufA);
    cudaGetSymbolAddress((void**)&bufB, g_bufB);

    const dim3 grid(BB / 4);   // 128 CTAs

    // Dynamic smem (weight overflow):
    //   L2: P=1, KSM=192 -> 192*256*4   = 196608 B  (R4-proven config)
    //   L3: P=4, KSM=16  -> 4*16*128*4  = 32768 B
    constexpr int DynL2 = 192 * 256 * 4;
    constexpr int DynL3 = 4 * 16 * 128 * 4;
    cudaFuncSetAttribute(rnn_layer<128, 256, 1, 192, 256, false>,
                         cudaFuncAttributeMaxDynamicSharedMemorySize, DynL2);
    cudaFuncSetAttribute(rnn_layer<256, 128, 4, 80, 512, false>,
                         cudaFuncAttributeMaxDynamicSharedMemorySize, DynL3);

    // L1: FIN=64,  H=128: 512 thr, P=4, KS=48, all 48 weights in regs
    rnn_layer<64, 128, 4, 48, 512, false><<<grid, 512, 0>>>(
        x, Wx1, Wh1, b1, bufA, nullptr, nullptr, nullptr);
    // L2: FIN=128, H=256: 256 thr, P=1, KS=384, 192 regs + 192 smem rows (R4 exact)
    rnn_layer<128, 256, 1, 192, 256, false><<<grid, 256, DynL2>>>(
        bufA, Wx2, Wh2, b2, bufB, nullptr, nullptr, nullptr);
    // L3: FIN=256, H=128: 512 thr, P=4, KS=96, 80 regs + 16 smem rows
    rnn_layer<256, 128, 4, 80, 512, false><<<grid, 512, DynL3>>>(
        bufB, Wx3, Wh3, b3, bufA, nullptr, nullptr, nullptr);
    // L4: FIN=128, H=64:  512 thr, P=8, KS=24, all regs, fused final dense
    rnn_layer<128, 64, 8, 24, 512, true><<<grid, 512, 0>>>(
        bufA, Wx4, Wh4, b4, nullptr, Wd, bd, out);
}

// round 10
// speedup vs baseline: 1.1448x; 1.0046x over previous
#include <cuda_runtime.h>

#define BB 512
#define TT 256

typedef unsigned long long u64;

// Inter-layer hidden sequences, batch-major [B, T, H]. Max H=256 -> 128 MB each.
__device__ float g_bufA[BB * TT * 256];
__device__ float g_bufB[BB * TT * 256];

__device__ __forceinline__ void ffma2(u64& d, u64 a, u64 b) {
    // packed fp32x2 fma: d.lo += a.lo*b.lo ; d.hi += a.hi*b.hi (IEEE per lane)
    asm("fma.rn.f32x2 %0, %1, %2, %0;" : "+l"(d) : "l"(a), "l"(b));
}

// ============================================================================
// SCALAR kernel (latency-friendly; best for L1/L3/L4).
// Thread (j, p) owns output column j and p-th k-slice; KREG weights in regs,
// KSM rows in dynamic smem. Acts k-major float4 (r0..r3); inner loop =
// 1 uniform LDS.128 + 4 FFMA per k.
// ============================================================================
template<int FIN, int H, int P, int KREG, int THREADS, bool FUSE_DENSE>
__global__ void __launch_bounds__(THREADS, 1)
rnn_layer(const float* __restrict__ x, const float* __restrict__ Wx,
          const float* __restrict__ Wh, const float* __restrict__ bias,
          float* __restrict__ hout, const float* __restrict__ Wd,
          const float* __restrict__ bd, float* __restrict__ out)
{
    constexpr int BT  = 4;
    constexpr int KV  = FIN + H;
    constexpr int KS  = KV / P;
    constexpr int KSM = KS - KREG;
    constexpr int CNT  = (BT * H + THREADS - 1) / THREADS;
    constexpr int CNTX = (BT * FIN + THREADS - 1) / THREADS;
    constexpr int REDN = FUSE_DENSE ? THREADS : 1;
    static_assert(H * P == THREADS, "thread count");
    static_assert(KV % P == 0 && KSM >= 0, "k partition");
    static_assert(!FUSE_DENSE || CNT == 1, "dense fusion assumes CNT==1");

    extern __shared__ float ws[];                       // [P][KSM][H]
    __shared__ __align__(16) float4 buf[2][KV];
    __shared__ float part[(P > 1 ? P : 1)][BT][(P > 1 ? H : 1)];
    __shared__ float red[REDN];

    const int tid = threadIdx.x;
    const int j   = tid % H;
    const int p   = tid / H;
    const int b0  = blockIdx.x * BT;
    const int k0  = p * KS;

    float w[KREG > 0 ? KREG : 1];
    #pragma unroll
    for (int q = 0; q < KREG; ++q) {
        int v = k0 + q;
        w[q] = (v < FIN) ? __ldg(&Wx[v * H + j]) : __ldg(&Wh[(v - FIN) * H + j]);
    }
    if (KSM > 0) {
        for (int idx = tid; idx < P * KSM * H; idx += THREADS) {
            int pp = idx / (KSM * H);
            int rem = idx % (KSM * H);
            int s = rem / H, jj = rem % H;
            int v = pp * KS + KREG + s;
            ws[idx] = (v < FIN) ? Wx[v * H + jj] : Wh[(v - FIN) * H + jj];
        }
    }
    for (int i = tid; i < H; i += THREADS) buf[0][FIN + i] = make_float4(0.f, 0.f, 0.f, 0.f);
    #pragma unroll
    for (int q = 0; q < CNTX; ++q) {
        int i = tid + q * THREADS;
        if (i < BT * FIN) {
            int r = i / FIN, k = i % FIN;
            ((float*)buf[0])[k * 4 + r] = __ldcg(&x[((b0 + r) * TT + 0) * FIN + k]);
        }
    }

    const float bjj = bias[j];
    float bj[CNT];
    #pragma unroll
    for (int q = 0; q < CNT; ++q) {
        int e = tid + q * THREADS;
        bj[q] = (e < BT * H) ? bias[e % H] : 0.f;
    }

    __syncthreads();

    float dacc = 0.f;
    int cb = 0;

    for (int t = 0; t < TT; ++t) {
        const int nb = cb ^ 1;

        float xst[CNTX];
        if (t + 1 < TT) {
            #pragma unroll
            for (int q = 0; q < CNTX; ++q) {
                int i = tid + q * THREADS;
                if (i < BT * FIN)
                    xst[q] = __ldcg(&x[((b0 + i / FIN) * TT + (t + 1)) * FIN + (i % FIN)]);
            }
        }

        float a0 = 0.f, a1 = 0.f, a2 = 0.f, a3 = 0.f;
        const float4* ub = buf[cb] + k0;

        #pragma unroll
        for (int q = 0; q < KREG; ++q) {
            float4 v = ub[q];
            a0 = fmaf(v.x, w[q], a0);
            a1 = fmaf(v.y, w[q], a1);
            a2 = fmaf(v.z, w[q], a2);
            a3 = fmaf(v.w, w[q], a3);
        }
        if (KSM > 0) {
            const float* wsp = ws + (p * KSM) * H + j;
            #pragma unroll 8
            for (int s = 0; s < KSM; ++s) {
                float4 v = ub[KREG + s];
                float wv = wsp[s * H];
                a0 = fmaf(v.x, wv, a0);
                a1 = fmaf(v.y, wv, a1);
                a2 = fmaf(v.z, wv, a2);
                a3 = fmaf(v.w, wv, a3);
            }
        }

        if (P == 1) {
            float4 hv;
            hv.x = fmaxf(a0 + bjj, 0.f);
            hv.y = fmaxf(a1 + bjj, 0.f);
            hv.z = fmaxf(a2 + bjj, 0.f);
            hv.w = fmaxf(a3 + bjj, 0.f);
            buf[nb][FIN + j] = hv;
            if (t + 1 < TT) {
                #pragma unroll
                for (int q = 0; q < CNTX; ++q) {
                    int i = tid + q * THREADS;
                    if (i < BT * FIN)
                        ((float*)buf[nb])[(i % FIN) * 4 + (i / FIN)] = xst[q];
                }
            }
            __stcg(&hout[((b0 + 0) * TT + t) * H + j], hv.x);
            __stcg(&hout[((b0 + 1) * TT + t) * H + j], hv.y);
            __stcg(&hout[((b0 + 2) * TT + t) * H + j], hv.z);
            __stcg(&hout[((b0 + 3) * TT + t) * H + j], hv.w);
            __syncthreads();
        } else {
            part[p][0][j] = a0;
            part[p][1][j] = a1;
            part[p][2][j] = a2;
            part[p][3][j] = a3;
            if (t + 1 < TT) {
                #pragma unroll
                for (int q = 0; q < CNTX; ++q) {
                    int i = tid + q * THREADS;
                    if (i < BT * FIN)
                        ((float*)buf[nb])[(i % FIN) * 4 + (i / FIN)] = xst[q];
                }
            }
            __syncthreads();
            #pragma unroll
            for (int q = 0; q < CNT; ++q) {
                int e = tid + q * THREADS;
                if (e < BT * H) {
                    int r = e / H, jj = e % H;
                    float s = bj[q];
                    #pragma unroll
                    for (int pp = 0; pp < P; ++pp) s += part[pp][r][jj];
                    s = fmaxf(s, 0.f);
                    ((float*)buf[nb])[(FIN + jj) * 4 + r] = s;
                    if (FUSE_DENSE) {
                        dacc = fmaf(s, __ldg(&Wd[t * H + jj]), dacc);
                    } else {
                        __stcg(&hout[((b0 + r) * TT + t) * H + jj], s);
                    }
                }
            }
            __syncthreads();
        }
        cb = nb;
    }

    if (FUSE_DENSE) {
        red[tid] = dacc;
        __syncthreads();
        if (tid < BT) {
            float s = bd[0];
            #pragma unroll 8
            for (int q = 0; q < H; ++q) s += red[tid * H + q];
            out[b0 + tid] = s;
        }
    }
}

// ============================================================================
// FFMA2 kernel (pipe-throughput-friendly; used ONLY for L2 where scalar FFMA
// issue is the binding term). Thread owns adjacent output-column pair; weight
// pairs adjacent in memory -> zero packing. Acts duplicated (v,v) in smem;
// inner loop per k = 2 uniform LDS.128 + 4 FFMA2 -> 8 outputs.
// ============================================================================
template<int FIN, int H, int P, int KREG, int THREADS, bool FUSE_DENSE>
__global__ void __launch_bounds__(THREADS, 1)
rnn_layer2(const float* __restrict__ x, const float* __restrict__ Wx,
           const float* __restrict__ Wh, const float* __restrict__ bias,
           float* __restrict__ hout, const float* __restrict__ Wd,
           const float* __restrict__ bd, float* __restrict__ out)
{
    constexpr int BT    = 4;
    constexpr int NPAIR = H / 2;
    constexpr int KV    = FIN + H;
    constexpr int KS    = KV / P;
    constexpr int KSM   = KS - KREG;
    constexpr int CNTX  = (BT * FIN + THREADS - 1) / THREADS;
    constexpr int CNT   = (BT * NPAIR + THREADS - 1) / THREADS;
    constexpr int REDN  = FUSE_DENSE ? THREADS : 1;
    static_assert(NPAIR * P == THREADS, "thread count");
    static_assert(KV % P == 0 && KSM >= 0, "k partition");
    static_assert(NPAIR % 32 == 0, "warp-uniform k per warp");
    static_assert(!FUSE_DENSE || CNT == 1, "dense fusion assumes CNT==1");

    extern __shared__ float2 wsm[];                       // [P][KSM][NPAIR]
    __shared__ __align__(16) float2 abuf[2][KV][BT];
    __shared__ __align__(16) float2 part[P][BT][NPAIR];
    __shared__ float red[REDN];

    const int tid = threadIdx.x;
    const int jp  = tid % NPAIR;
    const int p   = tid / NPAIR;
    const int b0  = blockIdx.x * BT;
    const int k0  = p * KS;

    u64 w[KREG > 0 ? KREG : 1];
    #pragma unroll
    for (int q = 0; q < KREG; ++q) {
        int v = k0 + q;
        const float* src = (v < FIN) ? &Wx[v * H + 2 * jp]
                                     : &Wh[(v - FIN) * H + 2 * jp];
        w[q] = *(const u64*)src;
    }
    if (KSM > 0) {
        for (int idx = tid; idx < P * KSM * NPAIR; idx += THREADS) {
            int pp = idx / (KSM * NPAIR);
            int s  = (idx / NPAIR) % KSM;
            int jj = idx % NPAIR;
            int v  = pp * KS + KREG + s;
            const float* src = (v < FIN) ? &Wx[v * H + 2 * jj]
                                         : &Wh[(v - FIN) * H + 2 * jj];
            wsm[idx] = *(const float2*)src;
        }
    }
    for (int i = tid; i < H * BT; i += THREADS)
        abuf[0][FIN + i / BT][i % BT] = make_float2(0.f, 0.f);
    #pragma unroll
    for (int q = 0; q < CNTX; ++q) {
        int i = tid + q * THREADS;
        if (i < BT * FIN) {
            int r = i / FIN, k = i % FIN;
            float v = __ldcg(&x[((b0 + r) * TT + 0) * FIN + k]);
            abuf[0][k][r] = make_float2(v, v);
        }
    }
    float2 b2[CNT];
    #pragma unroll
    for (int q = 0; q < CNT; ++q) {
        int e = tid + q * THREADS;
        b2[q] = (e < BT * NPAIR) ? *(const float2*)&bias[2 * (e % NPAIR)]
                                 : make_float2(0.f, 0.f);
    }

    __syncthreads();

    float dacc = 0.f;
    int cb = 0;

    for (int t = 0; t < TT; ++t) {
        const int nb = cb ^ 1;

        float xst[CNTX];
        if (t + 1 < TT) {
            #pragma unroll
            for (int q = 0; q < CNTX; ++q) {
                int i = tid + q * THREADS;
                if (i < BT * FIN)
                    xst[q] = __ldcg(&x[((b0 + i / FIN) * TT + (t + 1)) * FIN + (i % FIN)]);
            }
        }

        u64 a0 = 0, a1 = 0, a2 = 0, a3 = 0;

        #pragma unroll
        for (int q = 0; q < KREG; ++q) {
            const int k = k0 + q;
            ulonglong2 lo = *(const ulonglong2*)&abuf[cb][k][0];
            ulonglong2 hi = *(const ulonglong2*)&abuf[cb][k][2];
            ffma2(a0, lo.x, w[q]);
            ffma2(a1, lo.y, w[q]);
            ffma2(a2, hi.x, w[q]);
            ffma2(a3, hi.y, w[q]);
        }
        if (KSM > 0) {
            const float2* wp = wsm + (p * KSM) * NPAIR + jp;
            #pragma unroll 4
            for (int s = 0; s < KSM; ++s) {
                const int k = k0 + KREG + s;
                ulonglong2 lo = *(const ulonglong2*)&abuf[cb][k][0];
                ulonglong2 hi = *(const ulonglong2*)&abuf[cb][k][2];
                u64 wv = *(const u64*)&wp[s * NPAIR];
                ffma2(a0, lo.x, wv);
                ffma2(a1, lo.y, wv);
                ffma2(a2, hi.x, wv);
                ffma2(a3, hi.y, wv);
            }
        }

        part[p][0][jp] = *(float2*)&a0;
        part[p][1][jp] = *(float2*)&a1;
        part[p][2][jp] = *(float2*)&a2;
        part[p][3][jp] = *(float2*)&a3;
        if (t + 1 < TT) {
            #pragma unroll
            for (int q = 0; q < CNTX; ++q) {
                int i = tid + q * THREADS;
                if (i < BT * FIN)
                    abuf[nb][i % FIN][i / FIN] = make_float2(xst[q], xst[q]);
            }
        }
        __syncthreads();

        #pragma unroll
        for (int q = 0; q < CNT; ++q) {
            int e = tid + q * THREADS;
            if (e < BT * NPAIR) {
                int er = e / NPAIR, ej = e % NPAIR;
                float2 s = b2[q];
                #pragma unroll
                for (int pp = 0; pp < P; ++pp) {
                    float2 pv = part[pp][er][ej];
                    s.x += pv.x; s.y += pv.y;
                }
                s.x = fmaxf(s.x, 0.f);
                s.y = fmaxf(s.y, 0.f);
                abuf[nb][FIN + 2 * ej][er]     = make_float2(s.x, s.x);
                abuf[nb][FIN + 2 * ej + 1][er] = make_float2(s.y, s.y);
                if (FUSE_DENSE) {
                    float2 wd = *(const float2*)&Wd[t * H + 2 * ej];
                    dacc = fmaf(s.x, wd.x, fmaf(s.y, wd.y, dacc));
                } else {
                    __stcg((float2*)&hout[((b0 + er) * TT + t) * H + 2 * ej], s);
                }
            }
        }
        __syncthreads();
        cb = nb;
    }

    if (FUSE_DENSE) {
        red[tid] = dacc;
        __syncthreads();
        if (tid < BT) {
            float s = bd[0];
            #pragma unroll 8
            for (int i = 0; i < NPAIR; ++i) s += red[tid * NPAIR + i];
            out[b0 + tid] = s;
        }
    }
}

extern "C" void kernel_launch(void* const* d_in, const int* in_sizes, int n_in,
                              void* d_out, int out_size)
{
    (void)in_sizes; (void)n_in; (void)out_size;

    const float* x   = (const float*)d_in[0];
    const float* Wx1 = (const float*)d_in[1];
    const float* Wh1 = (const float*)d_in[2];
    const float* b1  = (const float*)d_in[3];
    const float* Wx2 = (const float*)d_in[4];
    const float* Wh2 = (const float*)d_in[5];
    const float* b2  = (const float*)d_in[6];
    const float* Wx3 = (const float*)d_in[7];
    const float* Wh3 = (const float*)d_in[8];
    const float* b3  = (const float*)d_in[9];
    const float* Wx4 = (const float*)d_in[10];
    const float* Wh4 = (const float*)d_in[11];
    const float* b4  = (const float*)d_in[12];
    const float* Wd  = (const float*)d_in[13];
    const float* bd  = (const float*)d_in[14];
    float* out = (float*)d_out;

    float *bufA = nullptr, *bufB = nullptr;
    cudaGetSymbolAddress((void**)&bufA, g_bufA);
    cudaGetSymbolAddress((void**)&bufB, g_bufB);

    const dim3 grid(BB / 4);   // 128 CTAs

    // Dynamic smem:
    //   L2 (FFMA2): P=2, KSM=92, NPAIR=128 -> 2*92*128*8 = 188416 B
    //   L3 (scalar): P=4, KSM=16           -> 4*16*128*4 = 32768 B
    constexpr int DynL2 = 2 * 92 * 128 * 8;
    constexpr int DynL3 = 4 * 16 * 128 * 4;
    cudaFuncSetAttribute(rnn_layer2<128, 256, 2, 100, 256, false>,
                         cudaFuncAttributeMaxDynamicSharedMemorySize, DynL2);
    cudaFuncSetAttribute(rnn_layer<256, 128, 4, 80, 512, false>,
                         cudaFuncAttributeMaxDynamicSharedMemorySize, DynL3);

    // L1: scalar, 512 thr, P=4, KS=48 all in regs (R8 best)
    rnn_layer<64, 128, 4, 48, 512, false><<<grid, 512, 0>>>(
        x, Wx1, Wh1, b1, bufA, nullptr, nullptr, nullptr);
    // L2: FFMA2, 256 thr, P=2, 100 reg-pairs + 92 smem rows (pipe-bound layer)
    rnn_layer2<128, 256, 2, 100, 256, false><<<grid, 256, DynL2>>>(
        bufA, Wx2, Wh2, b2, bufB, nullptr, nullptr, nullptr);
    // L3: scalar, 512 thr, P=4, 80 regs + 16 smem rows (R8 best)
    rnn_layer<256, 128, 4, 80, 512, false><<<grid, 512, DynL3>>>(
        bufB, Wx3, Wh3, b3, bufA, nullptr, nullptr, nullptr);
    // L4: scalar, 256 thr, P=4, KS=48 all in regs, fused dense (R4 best: 183us)
    rnn_layer<128, 64, 4, 48, 256, true><<<grid, 256, 0>>>(
        bufA, Wx4, Wh4, b4, nullptr, Wd, bd, out);
}

// round 11
// speedup vs baseline: 1.1924x; 1.0416x over previous
#include <cuda_runtime.h>

#define BB 512
#define TT 256

typedef unsigned long long u64;

// Inter-layer hidden sequences, batch-major [B, T, H]. Max H=256 -> 128 MB each.
__device__ float g_bufA[BB * TT * 256];
__device__ float g_bufB[BB * TT * 256];

__device__ __forceinline__ void ffma2(u64& d, u64 a, u64 b) {
    // packed fp32x2 fma: d.lo += a.lo*b.lo ; d.hi += a.hi*b.hi (IEEE per lane)
    asm("fma.rn.f32x2 %0, %1, %2, %0;" : "+l"(d) : "l"(a), "l"(b));
}
__device__ __forceinline__ u64 dup2(float w) {
    // (w, w) packed pair; 2 ALU-pipe MOVs, runs parallel to the fma pipe
    u64 r;
    unsigned int wu = __float_as_uint(w);
    asm("mov.b64 %0, {%1, %1};" : "=l"(r) : "r"(wu));
    return r;
}

// ============================================================================
// SCALAR kernel (latency-friendly; measured-best for L1/L3/L4).
// Thread (j, p) owns output column j and p-th k-slice; KREG weights in regs,
// KSM rows in dynamic smem. Acts k-major float4 (r0..r3); inner loop =
// 1 uniform LDS.128 + 4 FFMA per k.
// ============================================================================
template<int FIN, int H, int P, int KREG, int THREADS, bool FUSE_DENSE>
__global__ void __launch_bounds__(THREADS, 1)
rnn_layer(const float* __restrict__ x, const float* __restrict__ Wx,
          const float* __restrict__ Wh, const float* __restrict__ bias,
          float* __restrict__ hout, const float* __restrict__ Wd,
          const float* __restrict__ bd, float* __restrict__ out)
{
    constexpr int BT  = 4;
    constexpr int KV  = FIN + H;
    constexpr int KS  = KV / P;
    constexpr int KSM = KS - KREG;
    constexpr int CNT  = (BT * H + THREADS - 1) / THREADS;
    constexpr int CNTX = (BT * FIN + THREADS - 1) / THREADS;
    constexpr int REDN = FUSE_DENSE ? THREADS : 1;
    static_assert(H * P == THREADS, "thread count");
    static_assert(KV % P == 0 && KSM >= 0, "k partition");
    static_assert(!FUSE_DENSE || CNT == 1, "dense fusion assumes CNT==1");

    extern __shared__ float ws[];                       // [P][KSM][H]
    __shared__ __align__(16) float4 buf[2][KV];
    __shared__ float part[(P > 1 ? P : 1)][BT][(P > 1 ? H : 1)];
    __shared__ float red[REDN];

    const int tid = threadIdx.x;
    const int j   = tid % H;
    const int p   = tid / H;
    const int b0  = blockIdx.x * BT;
    const int k0  = p * KS;

    float w[KREG > 0 ? KREG : 1];
    #pragma unroll
    for (int q = 0; q < KREG; ++q) {
        int v = k0 + q;
        w[q] = (v < FIN) ? __ldg(&Wx[v * H + j]) : __ldg(&Wh[(v - FIN) * H + j]);
    }
    if (KSM > 0) {
        for (int idx = tid; idx < P * KSM * H; idx += THREADS) {
            int pp = idx / (KSM * H);
            int rem = idx % (KSM * H);
            int s = rem / H, jj = rem % H;
            int v = pp * KS + KREG + s;
            ws[idx] = (v < FIN) ? Wx[v * H + jj] : Wh[(v - FIN) * H + jj];
        }
    }
    for (int i = tid; i < H; i += THREADS) buf[0][FIN + i] = make_float4(0.f, 0.f, 0.f, 0.f);
    #pragma unroll
    for (int q = 0; q < CNTX; ++q) {
        int i = tid + q * THREADS;
        if (i < BT * FIN) {
            int r = i / FIN, k = i % FIN;
            ((float*)buf[0])[k * 4 + r] = __ldcg(&x[((b0 + r) * TT + 0) * FIN + k]);
        }
    }

    const float bjj = bias[j];
    float bj[CNT];
    #pragma unroll
    for (int q = 0; q < CNT; ++q) {
        int e = tid + q * THREADS;
        bj[q] = (e < BT * H) ? bias[e % H] : 0.f;
    }

    __syncthreads();

    float dacc = 0.f;
    int cb = 0;

    for (int t = 0; t < TT; ++t) {
        const int nb = cb ^ 1;

        float xst[CNTX];
        if (t + 1 < TT) {
            #pragma unroll
            for (int q = 0; q < CNTX; ++q) {
                int i = tid + q * THREADS;
                if (i < BT * FIN)
                    xst[q] = __ldcg(&x[((b0 + i / FIN) * TT + (t + 1)) * FIN + (i % FIN)]);
            }
        }

        float a0 = 0.f, a1 = 0.f, a2 = 0.f, a3 = 0.f;
        const float4* ub = buf[cb] + k0;

        #pragma unroll
        for (int q = 0; q < KREG; ++q) {
            float4 v = ub[q];
            a0 = fmaf(v.x, w[q], a0);
            a1 = fmaf(v.y, w[q], a1);
            a2 = fmaf(v.z, w[q], a2);
            a3 = fmaf(v.w, w[q], a3);
        }
        if (KSM > 0) {
            const float* wsp = ws + (p * KSM) * H + j;
            #pragma unroll 8
            for (int s = 0; s < KSM; ++s) {
                float4 v = ub[KREG + s];
                float wv = wsp[s * H];
                a0 = fmaf(v.x, wv, a0);
                a1 = fmaf(v.y, wv, a1);
                a2 = fmaf(v.z, wv, a2);
                a3 = fmaf(v.w, wv, a3);
            }
        }

        if (P == 1) {
            float4 hv;
            hv.x = fmaxf(a0 + bjj, 0.f);
            hv.y = fmaxf(a1 + bjj, 0.f);
            hv.z = fmaxf(a2 + bjj, 0.f);
            hv.w = fmaxf(a3 + bjj, 0.f);
            buf[nb][FIN + j] = hv;
            if (t + 1 < TT) {
                #pragma unroll
                for (int q = 0; q < CNTX; ++q) {
                    int i = tid + q * THREADS;
                    if (i < BT * FIN)
                        ((float*)buf[nb])[(i % FIN) * 4 + (i / FIN)] = xst[q];
                }
            }
            __stcg(&hout[((b0 + 0) * TT + t) * H + j], hv.x);
            __stcg(&hout[((b0 + 1) * TT + t) * H + j], hv.y);
            __stcg(&hout[((b0 + 2) * TT + t) * H + j], hv.z);
            __stcg(&hout[((b0 + 3) * TT + t) * H + j], hv.w);
            __syncthreads();
        } else {
            part[p][0][j] = a0;
            part[p][1][j] = a1;
            part[p][2][j] = a2;
            part[p][3][j] = a3;
            if (t + 1 < TT) {
                #pragma unroll
                for (int q = 0; q < CNTX; ++q) {
                    int i = tid + q * THREADS;
                    if (i < BT * FIN)
                        ((float*)buf[nb])[(i % FIN) * 4 + (i / FIN)] = xst[q];
                }
            }
            __syncthreads();
            #pragma unroll
            for (int q = 0; q < CNT; ++q) {
                int e = tid + q * THREADS;
                if (e < BT * H) {
                    int r = e / H, jj = e % H;
                    float s = bj[q];
                    #pragma unroll
                    for (int pp = 0; pp < P; ++pp) s += part[pp][r][jj];
                    s = fmaxf(s, 0.f);
                    ((float*)buf[nb])[(FIN + jj) * 4 + r] = s;
                    if (FUSE_DENSE) {
                        dacc = fmaf(s, __ldg(&Wd[t * H + jj]), dacc);
                    } else {
                        __stcg(&hout[((b0 + r) * TT + t) * H + jj], s);
                    }
                }
            }
            __syncthreads();
        }
        cb = nb;
    }

    if (FUSE_DENSE) {
        red[tid] = dacc;
        __syncthreads();
        if (tid < BT) {
            float s = bd[0];
            #pragma unroll 8
            for (int q = 0; q < H; ++q) s += red[tid * H + q];
            out[b0 + tid] = s;
        }
    }
}

// ============================================================================
// MOVDUP-FFMA2 kernel for layer 2 ONLY (the one FFMA-pipe-bound layer).
// Identical storage layout to the proven scalar L2 (KREG scalar weight regs,
// KSM scalar smem rows, non-duplicated float4 acts, P==1, one barrier/step).
// Inner loop per k: act float4 read as 2 u64 pairs (r0,r1|r2,r3); weight
// duplicated on the fly via mov.b64 {w,w} (2 ALU-pipe MOVs, parallel to fma
// pipe) + 2 FFMA2. fma-pipe load halves vs scalar; register footprint = scalar.
// ============================================================================
template<int FIN, int H, int KREG, int THREADS>
__global__ void __launch_bounds__(THREADS, 1)
rnn_layer_md(const float* __restrict__ x, const float* __restrict__ Wx,
             const float* __restrict__ Wh, const float* __restrict__ bias,
             float* __restrict__ hout)
{
    constexpr int BT  = 4;
    constexpr int KV  = FIN + H;
    constexpr int KSM = KV - KREG;
    constexpr int CNTX = (BT * FIN + THREADS - 1) / THREADS;
    static_assert(H == THREADS, "P==1: one thread per column");
    static_assert(KSM >= 0, "k partition");

    extern __shared__ float ws[];                       // [KSM][H]
    __shared__ __align__(16) float4 buf[2][KV];

    const int tid = threadIdx.x;
    const int j   = tid;
    const int b0  = blockIdx.x * BT;

    float w[KREG];
    #pragma unroll
    for (int q = 0; q < KREG; ++q) {
        int v = q;
        w[q] = (v < FIN) ? __ldg(&Wx[v * H + j]) : __ldg(&Wh[(v - FIN) * H + j]);
    }
    if (KSM > 0) {
        for (int idx = tid; idx < KSM * H; idx += THREADS) {
            int s = idx / H, jj = idx % H;
            int v = KREG + s;
            ws[idx] = (v < FIN) ? Wx[v * H + jj] : Wh[(v - FIN) * H + jj];
        }
    }
    for (int i = tid; i < H; i += THREADS) buf[0][FIN + i] = make_float4(0.f, 0.f, 0.f, 0.f);
    #pragma unroll
    for (int q = 0; q < CNTX; ++q) {
        int i = tid + q * THREADS;
        if (i < BT * FIN) {
            int r = i / FIN, k = i % FIN;
            ((float*)buf[0])[k * 4 + r] = __ldcg(&x[((b0 + r) * TT + 0) * FIN + k]);
        }
    }
    const float bjj = bias[j];

    __syncthreads();

    int cb = 0;

    for (int t = 0; t < TT; ++t) {
        const int nb = cb ^ 1;

        float xst[CNTX];
        if (t + 1 < TT) {
            #pragma unroll
            for (int q = 0; q < CNTX; ++q) {
                int i = tid + q * THREADS;
                if (i < BT * FIN)
                    xst[q] = __ldcg(&x[((b0 + i / FIN) * TT + (t + 1)) * FIN + (i % FIN)]);
            }
        }

        u64 a01 = 0, a23 = 0;               // packed accumulators (r0,r1)(r2,r3)
        const ulonglong2* ub = (const ulonglong2*)buf[cb];

        #pragma unroll
        for (int q = 0; q < KREG; ++q) {            // register weights
            ulonglong2 av = ub[q];                  // LDS.128, warp-uniform
            u64 wp = dup2(w[q]);                    // 2 ALU movs, parallel pipe
            ffma2(a01, av.x, wp);
            ffma2(a23, av.y, wp);
        }
        if (KSM > 0) {                               // smem weights
            const float* wsp = ws + j;
            #pragma unroll 8
            for (int s = 0; s < KSM; ++s) {
                ulonglong2 av = ub[KREG + s];
                u64 wp = dup2(wsp[s * H]);
                ffma2(a01, av.x, wp);
                ffma2(a23, av.y, wp);
            }
        }

        float2 f01 = *(float2*)&a01;
        float2 f23 = *(float2*)&a23;
        float4 hv;
        hv.x = fmaxf(f01.x + bjj, 0.f);
        hv.y = fmaxf(f01.y + bjj, 0.f);
        hv.z = fmaxf(f23.x + bjj, 0.f);
        hv.w = fmaxf(f23.y + bjj, 0.f);
        buf[nb][FIN + j] = hv;                       // STS.128
        if (t + 1 < TT) {
            #pragma unroll
            for (int q = 0; q < CNTX; ++q) {
                int i = tid + q * THREADS;
                if (i < BT * FIN)
                    ((float*)buf[nb])[(i % FIN) * 4 + (i / FIN)] = xst[q];
            }
        }
        __stcg(&hout[((b0 + 0) * TT + t) * H + j], hv.x);
        __stcg(&hout[((b0 + 1) * TT + t) * H + j], hv.y);
        __stcg(&hout[((b0 + 2) * TT + t) * H + j], hv.z);
        __stcg(&hout[((b0 + 3) * TT + t) * H + j], hv.w);
        __syncthreads();                             // ONE barrier per step
        cb = nb;
    }
}

extern "C" void kernel_launch(void* const* d_in, const int* in_sizes, int n_in,
                              void* d_out, int out_size)
{
    (void)in_sizes; (void)n_in; (void)out_size;

    const float* x   = (const float*)d_in[0];
    const float* Wx1 = (const float*)d_in[1];
    const float* Wh1 = (const float*)d_in[2];
    const float* b1  = (const float*)d_in[3];
    const float* Wx2 = (const float*)d_in[4];
    const float* Wh2 = (const float*)d_in[5];
    const float* b2  = (const float*)d_in[6];
    const float* Wx3 = (const float*)d_in[7];
    const float* Wh3 = (const float*)d_in[8];
    const float* b3  = (const float*)d_in[9];
    const float* Wx4 = (const float*)d_in[10];
    const float* Wh4 = (const float*)d_in[11];
    const float* b4  = (const float*)d_in[12];
    const float* Wd  = (const float*)d_in[13];
    const float* bd  = (const float*)d_in[14];
    float* out = (float*)d_out;

    float *bufA = nullptr, *bufB = nullptr;
    cudaGetSymbolAddress((void**)&bufA, g_bufA);
    cudaGetSymbolAddress((void**)&bufB, g_bufB);

    const dim3 grid(BB / 4);   // 128 CTAs

    // Dynamic smem (weight overflow):
    //   L2 (movdup): KSM=192 -> 192*256*4  = 196608 B
    //   L3 (scalar): P=4, KSM=16 -> 4*16*128*4 = 32768 B
    constexpr int DynL2 = 192 * 256 * 4;
    constexpr int DynL3 = 4 * 16 * 128 * 4;
    cudaFuncSetAttribute(rnn_layer_md<128, 256, 192, 256>,
                         cudaFuncAttributeMaxDynamicSharedMemorySize, DynL2);
    cudaFuncSetAttribute(rnn_layer<256, 128, 4, 80, 512, false>,
                         cudaFuncAttributeMaxDynamicSharedMemorySize, DynL3);

    // L1: scalar, 512 thr, P=4, KS=48 all in regs (R8 measured best)
    rnn_layer<64, 128, 4, 48, 512, false><<<grid, 512, 0>>>(
        x, Wx1, Wh1, b1, bufA, nullptr, nullptr, nullptr);
    // L2: movdup FFMA2, 256 thr, P=1, 192 weight regs + 192 smem rows
    rnn_layer_md<128, 256, 192, 256><<<grid, 256, DynL2>>>(
        bufA, Wx2, Wh2, b2, bufB);
    // L3: scalar, 512 thr, P=4, 80 regs + 16 smem rows (R8 measured best)
    rnn_layer<256, 128, 4, 80, 512, false><<<grid, 512, DynL3>>>(
        bufB, Wx3, Wh3, b3, bufA, nullptr, nullptr, nullptr);
    // L4: scalar, 256 thr, P=4, KS=48 all in regs, fused dense (183us measured)
    rnn_layer<128, 64, 4, 48, 256, true><<<grid, 256, 0>>>(
        bufA, Wx4, Wh4, b4, nullptr, Wd, bd, out);
}